// round 9
// baseline (speedup 1.0000x reference)
#include <cuda_runtime.h>
#include <cstdint>

// Problem constants
#define Bc 32
#define Dc 256
#define Tc 2048
#define Lc 8
#define Kc 1024
#define Nc (Bc * Tc)            // 65536 vectors
#define OUT_ELEMS ((size_t)Bc * Dc * Tc)   // 16,777,216 floats
#define IDX_OFF   OUT_ELEMS                 // indices start here (B, L, T) as float

// Scratch (no allocations allowed -> __device__ globals)
__device__ float g_resid[(size_t)Nc * Dc];   // 64 MB residual buffer
__device__ float g_wnorm[Lc * Kc];           // |W|^2 per codeword (XLA-exact rounding)

// ---------------------------------------------------------------------------
// XLA row-reduce replica for width=256 f32 (sum of squares):
//   128 threads per row, vec=2 contiguous: p_t = fl(x[2t]^2 + x[2t+1]^2)
//   intra-warp shfl_down tree (16,8,4,2,1), cross-warp: fl(fl(w0+w2)+fl(w1+w3))
// All adds/muls via __fadd_rn/__fmul_rn (no fma contraction), matching XLA
// codegen (separate mul + reduce-add HLOs, no contract fast-math flags).
// ---------------------------------------------------------------------------

// wnorm: one block of 256 threads handles 2 codebook rows (two 4-warp groups).
__global__ void wnorm_kernel(const float* __restrict__ cb) {
    __shared__ float s_wp[2][4];
    int t128 = threadIdx.x & 127;          // position within 4-warp group
    int g    = threadIdx.x >> 7;           // group 0/1
    int lane = threadIdx.x & 31;
    int wIG  = t128 >> 5;                  // warp within group, 0..3
    int row  = blockIdx.x * 2 + g;         // row in [0, L*K)

    const float* w = cb + (size_t)row * Dc;
    float2 v = *(const float2*)&w[t128 * 2];
    float p = __fadd_rn(__fmul_rn(v.x, v.x), __fmul_rn(v.y, v.y));
#pragma unroll
    for (int off = 16; off; off >>= 1)
        p = __fadd_rn(p, __shfl_down_sync(0xffffffffu, p, off));
    if (lane == 0) s_wp[g][wIG] = p;
    __syncthreads();
    if (t128 == 0) {
        float w0 = s_wp[g][0], w1 = s_wp[g][1], w2 = s_wp[g][2], w3 = s_wp[g][3];
        g_wnorm[row] = __fadd_rn(__fadd_rn(w0, w2), __fadd_rn(w1, w3));
    }
}

// ---------------------------------------------------------------------------
// Kernel: transpose x (B, D, T) -> resid (N, D), N = B*T, n = b*T + t
// ---------------------------------------------------------------------------
__global__ void transpose_in_kernel(const float* __restrict__ x) {
    __shared__ float tile[32][33];
    int b  = blockIdx.z;
    int d0 = blockIdx.y * 32;
    int t0 = blockIdx.x * 32;
    int tx = threadIdx.x, ty = threadIdx.y;
#pragma unroll
    for (int j = 0; j < 32; j += 8) {
        int d = d0 + ty + j;
        tile[ty + j][tx] = x[((size_t)b * Dc + d) * Tc + t0 + tx];
    }
    __syncthreads();
#pragma unroll
    for (int j = 0; j < 32; j += 8) {
        int t = t0 + ty + j;
        g_resid[((size_t)(b * Tc + t)) * Dc + d0 + tx] = tile[tx][ty + j];
    }
}

// ---------------------------------------------------------------------------
// Kernel: finalize. out[b,d,t] = x[b,d,t] - resid[n,d]   (out = r0 - r_L)
// ---------------------------------------------------------------------------
__global__ void finalize_kernel(const float* __restrict__ x, float* __restrict__ out) {
    __shared__ float tile[32][33];
    int b  = blockIdx.z;
    int d0 = blockIdx.y * 32;
    int t0 = blockIdx.x * 32;
    int tx = threadIdx.x, ty = threadIdx.y;
#pragma unroll
    for (int j = 0; j < 32; j += 8) {
        int t = t0 + ty + j;
        tile[ty + j][tx] = g_resid[((size_t)(b * Tc + t)) * Dc + d0 + tx];
    }
    __syncthreads();
#pragma unroll
    for (int j = 0; j < 32; j += 8) {
        int d = d0 + ty + j;
        size_t idx = ((size_t)b * Dc + d) * Tc + t0 + tx;
        out[idx] = x[idx] - tile[tx][ty + j];
    }
}

// ---------------------------------------------------------------------------
// Layer kernel. 128 rows per block. Bit-exact replication of the reference:
//   M     = r . W  via serial-k ascending FFMA chain (== cuBLAS sgemm)
//   rr    = XLA row-reduce of r*r (pattern above)
//   ww    = precomputed XLA row-reduce of W*W
//   dist2 = fl( fl( rr - fl(2*M) ) + ww )
//   argmin: first-min tie-break (== jnp.argmin)
// Then index emit + exact fp32 residual update.
// ---------------------------------------------------------------------------
__global__ __launch_bounds__(256, 2)
void layer_kernel(const float* __restrict__ cb, int l, float* __restrict__ dout) {
    __shared__ __align__(16) float As[32][132];
    __shared__ __align__(16) float Bs[32][132];
    __shared__ float s_wp[128][4];
    __shared__ float s_rr[128];
    __shared__ int   s_idx[128];

    const int tid = threadIdx.x;
    const int tx = tid & 15;        // column group
    const int ty = tid >> 4;        // row group
    const int rowBase = blockIdx.x * 128;
    const float* W = cb + (size_t)l * Kc * Dc;
    const float* wn_l = g_wnorm + l * Kc;

    // ---- rr for the block's 128 rows, XLA-exact --------------------------
    {
        int t128 = tid & 127;
        int g    = tid >> 7;            // two independent 4-warp groups
        int lane = tid & 31;
        int wIG  = t128 >> 5;
#pragma unroll 1
        for (int rp = 0; rp < 64; ++rp) {
            int row = rp * 2 + g;
            const float* rrow = &g_resid[((size_t)(rowBase + row)) * Dc];
            float2 v = *(const float2*)&rrow[t128 * 2];
            float p = __fadd_rn(__fmul_rn(v.x, v.x), __fmul_rn(v.y, v.y));
#pragma unroll
            for (int off = 16; off; off >>= 1)
                p = __fadd_rn(p, __shfl_down_sync(0xffffffffu, p, off));
            if (lane == 0) s_wp[row][wIG] = p;
        }
        __syncthreads();
        if (tid < 128) {
            float w0 = s_wp[tid][0], w1 = s_wp[tid][1];
            float w2 = s_wp[tid][2], w3 = s_wp[tid][3];
            s_rr[tid] = __fadd_rn(__fadd_rn(w0, w2), __fadd_rn(w1, w3));
        }
        __syncthreads();
    }

    float best[8];
    int   barg[8];
#pragma unroll
    for (int i = 0; i < 8; ++i) { best[i] = 3.4e38f; barg[i] = 0; }

    float rr_reg[8];
#pragma unroll
    for (int i = 0; i < 8; ++i) rr_reg[i] = s_rr[ty * 8 + i];

    for (int nt = 0; nt < 8; ++nt) {
        const int nBase = nt * 128;
        float acc[8][8];
#pragma unroll
        for (int i = 0; i < 8; ++i)
#pragma unroll
            for (int j = 0; j < 8; ++j) acc[i][j] = 0.f;

        for (int kt = 0; kt < Dc; kt += 32) {
            // Stage A (residual rows) and B (codeword rows), transposed into smem.
#pragma unroll
            for (int q = 0; q < 4; ++q) {
                int e  = tid + q * 256;        // e in [0,1024)
                int row = e >> 3;              // 0..127
                int c4  = e & 7;               // which float4 of the 32-wide chunk
                float4 va = *(const float4*)&g_resid[((size_t)(rowBase + row)) * Dc + kt + c4 * 4];
                As[c4 * 4 + 0][row] = va.x;
                As[c4 * 4 + 1][row] = va.y;
                As[c4 * 4 + 2][row] = va.z;
                As[c4 * 4 + 3][row] = va.w;
                float4 vb = *(const float4*)&W[((size_t)(nBase + row)) * Dc + kt + c4 * 4];
                Bs[c4 * 4 + 0][row] = vb.x;
                Bs[c4 * 4 + 1][row] = vb.y;
                Bs[c4 * 4 + 2][row] = vb.z;
                Bs[c4 * 4 + 3][row] = vb.w;
            }
            __syncthreads();

#pragma unroll
            for (int kk = 0; kk < 32; ++kk) {
                float a[8], bv[8];
                float4 a0 = *(const float4*)&As[kk][ty * 8];
                float4 a1 = *(const float4*)&As[kk][ty * 8 + 4];
                float4 b0 = *(const float4*)&Bs[kk][tx * 8];
                float4 b1 = *(const float4*)&Bs[kk][tx * 8 + 4];
                a[0]=a0.x; a[1]=a0.y; a[2]=a0.z; a[3]=a0.w;
                a[4]=a1.x; a[5]=a1.y; a[6]=a1.z; a[7]=a1.w;
                bv[0]=b0.x; bv[1]=b0.y; bv[2]=b0.z; bv[3]=b0.w;
                bv[4]=b1.x; bv[5]=b1.y; bv[6]=b1.z; bv[7]=b1.w;
#pragma unroll
                for (int i = 0; i < 8; ++i)
#pragma unroll
                    for (int j = 0; j < 8; ++j)
                        acc[i][j] = fmaf(a[i], bv[j], acc[i][j]);   // == cuBLAS FFMA chain
            }
            __syncthreads();
        }

        // Fold this 128-column tile into the running per-row minimum,
        // with the reference's exact rounding: fl(fl(rr - 2M) + ww).
#pragma unroll
        for (int j = 0; j < 8; ++j) {
            int c = nBase + tx * 8 + j;
            float wn = wn_l[c];
#pragma unroll
            for (int i = 0; i < 8; ++i) {
                float m2 = __fmul_rn(-2.f, acc[i][j]);       // exact
                float s  = __fadd_rn(__fadd_rn(rr_reg[i], m2), wn);
                if (s < best[i]) { best[i] = s; barg[i] = c; }   // strict <: lowest col wins ties
            }
        }
    }

    // Reduce argmin across the 16 column-group threads (same ty -> 16 lanes).
#pragma unroll
    for (int i = 0; i < 8; ++i) {
        float v = best[i];
        int   g = barg[i];
#pragma unroll
        for (int off = 8; off; off >>= 1) {
            float ov = __shfl_down_sync(0xffffffffu, v, off, 16);
            int   og = __shfl_down_sync(0xffffffffu, g, off, 16);
            if (ov < v || (ov == v && og < g)) { v = ov; g = og; }
        }
        if (tx == 0) s_idx[ty * 8 + i] = g;
    }
    __syncthreads();

    // Emit indices into d_out (B, L, T) region (as float).
    if (tid < 128) {
        int n = rowBase + tid;
        int b = n >> 11;             // / 2048
        int t = n & 2047;
        dout[IDX_OFF + ((size_t)b * Lc + l) * Tc + t] = (float)s_idx[tid];
    }

    // Residual update: resid[row] -= W[idx[row]] (exact fp32). float4 vectorized.
    for (int e = tid; e < 128 * (Dc / 4); e += 256) {
        int row = e >> 6;            // Dc/4 = 64
        int c   = e & 63;
        float4* rp = (float4*)&g_resid[((size_t)(rowBase + row)) * Dc] + c;
        const float4* wp = (const float4*)&W[((size_t)s_idx[row]) * Dc] + c;
        float4 rv = *rp;
        float4 wv = *wp;
        rv.x -= wv.x; rv.y -= wv.y; rv.z -= wv.z; rv.w -= wv.w;
        *rp = rv;
    }
}

// ---------------------------------------------------------------------------
extern "C" void kernel_launch(void* const* d_in, const int* in_sizes, int n_in,
                              void* d_out, int out_size) {
    const float* x  = (const float*)d_in[0];
    const float* cb = (const float*)d_in[1];
    // Defensive: setup_inputs order is (x, codebooks); swap if sizes say otherwise.
    if (n_in >= 2 && in_sizes[0] == Lc * Kc * Dc && in_sizes[1] == Bc * Dc * Tc) {
        const float* tmp = x; x = cb; cb = tmp;
    }
    float* out = (float*)d_out;

    // 1. codeword norms (XLA-exact rounding)
    wnorm_kernel<<<(Lc * Kc) / 2, 256>>>(cb);

    // 2. x -> residual (N, D)
    {
        dim3 grid(Tc / 32, Dc / 32, Bc);
        dim3 block(32, 8);
        transpose_in_kernel<<<grid, block>>>(x);
    }

    // 3. eight sequential VQ layers
    for (int l = 0; l < Lc; ++l) {
        layer_kernel<<<Nc / 128, 256>>>(cb, l, out);
    }

    // 4. out = x - final residual
    {
        dim3 grid(Tc / 32, Dc / 32, Bc);
        dim3 block(32, 8);
        finalize_kernel<<<grid, block>>>(x, out);
    }
}

// round 11
// speedup vs baseline: 2.4393x; 2.4393x over previous
#include <cuda_runtime.h>
#include <cuda_fp16.h>
#include <cstdint>
#include <cfloat>

// Problem constants
#define Bc 32
#define Dc 256
#define Tc 2048
#define Lc 8
#define Kc 1024
#define Nc (Bc * Tc)
#define OUT_ELEMS ((size_t)Bc * Dc * Tc)
#define IDX_OFF   OUT_ELEMS

// Scratch (no allocations allowed -> __device__ globals)
__device__ float g_resid[(size_t)Nc * Dc];            // 64 MB residual (L2-resident)
__device__ float g_wnorm[Lc * Kc];                    // |W|^2, XLA-exact
__device__ __align__(16) __half g_Wh[(size_t)Lc * Kc * Dc];  // fp16 codebooks (4 MB)

// smem layout (bytes)
#define SM_WW   0          // 1024 f32            4096
#define SM_RR   4096       // 128 f32             512
#define SM_WP   4608       // 128*4 f32           2048
#define SM_CAND 6656       // 128*4 int           2048
#define SM_IDX  8704       // 128 int             512
#define SM_A    9216       // 128 x 264 half      67584
#define SM_B    76800      // 64 x 264 half       33792
#define SMEM_TOTAL 110592
#define PA 264             // halves pitch (528B: conflict-free ldmatrix)

__device__ __forceinline__ uint32_t smem_to_u32(const void* p) {
    uint32_t a;
    asm("{ .reg .u64 t; cvta.to.shared.u64 t, %1; cvt.u32.u64 %0, t; }" : "=r"(a) : "l"(p));
    return a;
}
__device__ __forceinline__ void ldsm_x4(uint32_t& r0, uint32_t& r1, uint32_t& r2, uint32_t& r3, uint32_t addr) {
    asm volatile("ldmatrix.sync.aligned.m8n8.x4.shared.b16 {%0,%1,%2,%3}, [%4];"
                 : "=r"(r0), "=r"(r1), "=r"(r2), "=r"(r3) : "r"(addr));
}
__device__ __forceinline__ void mma16816(float* c, uint32_t a0, uint32_t a1, uint32_t a2, uint32_t a3,
                                         uint32_t b0, uint32_t b1) {
    asm volatile("mma.sync.aligned.m16n8k16.row.col.f32.f16.f16.f32 "
                 "{%0,%1,%2,%3}, {%4,%5,%6,%7}, {%8,%9}, {%0,%1,%2,%3};"
                 : "+f"(c[0]), "+f"(c[1]), "+f"(c[2]), "+f"(c[3])
                 : "r"(a0), "r"(a1), "r"(a2), "r"(a3), "r"(b0), "r"(b1));
}

// ===========================================================================
// Prep kernels
// ===========================================================================
__global__ void wprep_kernel(const float* __restrict__ cb) {
    size_t total = (size_t)Lc * Kc * Dc;
    for (size_t i = (size_t)blockIdx.x * blockDim.x + threadIdx.x; i < total;
         i += (size_t)gridDim.x * blockDim.x)
        g_Wh[i] = __float2half_rn(cb[i]);
}

// wnorm: XLA-exact |W|^2 (validated round 9)
__global__ void wnorm_kernel(const float* __restrict__ cb) {
    __shared__ float s_wp[2][4];
    int t128 = threadIdx.x & 127;
    int g    = threadIdx.x >> 7;
    int lane = threadIdx.x & 31;
    int wIG  = t128 >> 5;
    int row  = blockIdx.x * 2 + g;
    const float* w = cb + (size_t)row * Dc;
    float2 v = *(const float2*)&w[t128 * 2];
    float p = __fadd_rn(__fmul_rn(v.x, v.x), __fmul_rn(v.y, v.y));
#pragma unroll
    for (int off = 16; off; off >>= 1)
        p = __fadd_rn(p, __shfl_down_sync(0xffffffffu, p, off));
    if (lane == 0) s_wp[g][wIG] = p;
    __syncthreads();
    if (t128 == 0) {
        float w0 = s_wp[g][0], w1 = s_wp[g][1], w2 = s_wp[g][2], w3 = s_wp[g][3];
        g_wnorm[row] = __fadd_rn(__fadd_rn(w0, w2), __fadd_rn(w1, w3));
    }
}

__global__ void transpose_in_kernel(const float* __restrict__ x) {
    __shared__ float tile[32][33];
    int b = blockIdx.z, d0 = blockIdx.y * 32, t0 = blockIdx.x * 32;
    int tx = threadIdx.x, ty = threadIdx.y;
#pragma unroll
    for (int j = 0; j < 32; j += 8)
        tile[ty + j][tx] = x[((size_t)b * Dc + d0 + ty + j) * Tc + t0 + tx];
    __syncthreads();
#pragma unroll
    for (int j = 0; j < 32; j += 8)
        g_resid[((size_t)(b * Tc + t0 + ty + j)) * Dc + d0 + tx] = tile[tx][ty + j];
}

__global__ void finalize_kernel(const float* __restrict__ x, float* __restrict__ out) {
    __shared__ float tile[32][33];
    int b = blockIdx.z, d0 = blockIdx.y * 32, t0 = blockIdx.x * 32;
    int tx = threadIdx.x, ty = threadIdx.y;
#pragma unroll
    for (int j = 0; j < 32; j += 8)
        tile[ty + j][tx] = g_resid[((size_t)(b * Tc + t0 + ty + j)) * Dc + d0 + tx];
    __syncthreads();
#pragma unroll
    for (int j = 0; j < 32; j += 8) {
        size_t idx = ((size_t)b * Dc + d0 + ty + j) * Tc + t0 + tx;
        out[idx] = x[idx] - tile[tx][ty + j];
    }
}

// tie-aware insert into ascending top-4 (lower col wins ties)
__device__ __forceinline__ void ins4(float s, int col, float* v, int* c) {
    if (s < v[3] || (s == v[3] && col < c[3])) {
        if (s < v[2] || (s == v[2] && col < c[2])) {
            v[3] = v[2]; c[3] = c[2];
            if (s < v[1] || (s == v[1] && col < c[1])) {
                v[2] = v[1]; c[2] = c[1];
                if (s < v[0] || (s == v[0] && col < c[0])) {
                    v[1] = v[0]; c[1] = c[0]; v[0] = s; c[0] = col;
                } else { v[1] = s; c[1] = col; }
            } else { v[2] = s; c[2] = col; }
        } else { v[3] = s; c[3] = col; }
    }
}

// ===========================================================================
// Fused RVQ kernel: all 8 layers. 512 CTAs x 128 rows, 256 threads (8 warps).
// Per layer: fp16 HMMA prefilter (score = ww - 2 r.W) -> per-row noisy top-4
// -> exact rescore (bit-identical to reference arithmetic) -> index + update.
// ===========================================================================
__global__ __launch_bounds__(256, 2)
void rvq_fused_kernel(const float* __restrict__ cb, float* __restrict__ dout) {
    extern __shared__ char smem[];
    const uint32_t su = smem_to_u32(smem);
    float* s_ww = (float*)(smem + SM_WW);
    float* s_rr = (float*)(smem + SM_RR);
    float* s_wp = (float*)(smem + SM_WP);
    int*   s_cand = (int*)(smem + SM_CAND);
    int*   s_idx  = (int*)(smem + SM_IDX);

    const int tid = threadIdx.x;
    const int wid = tid >> 5;
    const int lane = tid & 31;
    const int rowBase = blockIdx.x * 128;

    // ldmatrix lane-fixed address components
    // A: row = 16*wid + (lane&15), koff = (lane>>4)*8
    const uint32_t aLaneBase = su + SM_A + (uint32_t)(((wid << 4) + (lane & 15)) * PA + ((lane >> 4) << 3)) * 2;
    // B: nrow = ((lane>>4)<<3) + (lane&7), koff = ((lane>>3)&1)*8
    const uint32_t bLaneBase = su + SM_B + (uint32_t)(((((lane >> 4) << 3) + (lane & 7)) * PA) + (((lane >> 3) & 1) << 3)) * 2;

    for (int l = 0; l < Lc; ++l) {
        const int lRow = l * Kc;

        // ---- rr (XLA-exact, validated) ------------------------------------
        {
            int t128 = tid & 127;
            int g    = tid >> 7;
            int wIG  = t128 >> 5;
#pragma unroll 1
            for (int rp = 0; rp < 64; ++rp) {
                int row = rp * 2 + g;
                const float* rrow = &g_resid[((size_t)(rowBase + row)) * Dc];
                float2 v = *(const float2*)&rrow[t128 * 2];
                float p = __fadd_rn(__fmul_rn(v.x, v.x), __fmul_rn(v.y, v.y));
#pragma unroll
                for (int off = 16; off; off >>= 1)
                    p = __fadd_rn(p, __shfl_down_sync(0xffffffffu, p, off));
                if ((lane & 31) == 0) s_wp[row * 4 + wIG] = p;
            }
            __syncthreads();
            if (tid < 128) {
                float w0 = s_wp[tid*4+0], w1 = s_wp[tid*4+1];
                float w2 = s_wp[tid*4+2], w3 = s_wp[tid*4+3];
                s_rr[tid] = __fadd_rn(__fadd_rn(w0, w2), __fadd_rn(w1, w3));
            }
        }

        // ---- stage ww + A(fp16) -------------------------------------------
        *(float4*)&s_ww[tid * 4] = *(const float4*)(g_wnorm + lRow + tid * 4);
#pragma unroll
        for (int i = 0; i < 16; ++i) {
            int u = tid + i * 256;          // 4096 units of 8 floats
            int row = u >> 5;
            int k0  = (u & 31) << 3;
            const float4* src = (const float4*)(g_resid + ((size_t)(rowBase + row)) * Dc + k0);
            float4 v0 = src[0], v1 = src[1];
            __half2 h0 = __float22half2_rn(make_float2(v0.x, v0.y));
            __half2 h1 = __float22half2_rn(make_float2(v0.z, v0.w));
            __half2 h2 = __float22half2_rn(make_float2(v1.x, v1.y));
            __half2 h3 = __float22half2_rn(make_float2(v1.z, v1.w));
            *(uint4*)(smem + SM_A + (size_t)(row * PA + k0) * 2) =
                make_uint4(*(uint32_t*)&h0, *(uint32_t*)&h1, *(uint32_t*)&h2, *(uint32_t*)&h3);
        }
        __syncthreads();

        // per-row noisy top-4 (2 rows/thread: rA = 16*wid + (lane>>2), rA+8)
        float tv0[4], tv1[4];
        int   tc0[4], tc1[4];
#pragma unroll
        for (int j = 0; j < 4; ++j) {
            tv0[j] = FLT_MAX; tv1[j] = FLT_MAX; tc0[j] = 1 << 30; tc1[j] = 1 << 30;
        }

        // ---- 16 chunks of 64 codewords ------------------------------------
        for (int ch = 0; ch < 16; ++ch) {
            // stage B chunk: 64 rows x 256 halves from g_Wh
#pragma unroll
            for (int i = 0; i < 8; ++i) {
                int u = tid + i * 256;      // 2048 units of 8 halves
                int row = u >> 5;
                int k0  = (u & 31) << 3;
                uint4 v = *(const uint4*)(g_Wh + ((size_t)(lRow + ch * 64 + row)) * Dc + k0);
                *(uint4*)(smem + SM_B + (size_t)(row * PA + k0) * 2) = v;
            }
            __syncthreads();

            float acc[8][4];
#pragma unroll
            for (int n = 0; n < 8; ++n)
#pragma unroll
                for (int j = 0; j < 4; ++j) acc[n][j] = 0.f;

#pragma unroll 4
            for (int ks = 0; ks < 16; ++ks) {
                uint32_t a0, a1, a2, a3;
                ldsm_x4(a0, a1, a2, a3, aLaneBase + ks * 32);
#pragma unroll
                for (int p = 0; p < 4; ++p) {
                    uint32_t r0, r1, r2, r3;
                    ldsm_x4(r0, r1, r2, r3, bLaneBase + (uint32_t)(p * 16 * PA) * 2 + ks * 32);
                    mma16816(acc[2 * p],     a0, a1, a2, a3, r0, r1);
                    mma16816(acc[2 * p + 1], a0, a1, a2, a3, r2, r3);
                }
            }

            // epilogue: fold into top-4 (cols ascending => strict < keeps low col)
#pragma unroll
            for (int n = 0; n < 8; ++n) {
                int cbase = ch * 64 + n * 8 + ((lane & 3) << 1);
                float ww0 = s_ww[cbase], ww1 = s_ww[cbase + 1];
                float s00 = fmaf(-2.f, acc[n][0], ww0);
                float s01 = fmaf(-2.f, acc[n][1], ww1);
                float s10 = fmaf(-2.f, acc[n][2], ww0);
                float s11 = fmaf(-2.f, acc[n][3], ww1);
                ins4(s00, cbase,     tv0, tc0);
                ins4(s01, cbase + 1, tv0, tc0);
                ins4(s10, cbase,     tv1, tc1);
                ins4(s11, cbase + 1, tv1, tc1);
            }
            __syncthreads();
        }

        // ---- quad gather: lane q0 of each quad merges 3 partners ----------
        {
#pragma unroll
            for (int src = 1; src < 4; ++src) {
#pragma unroll
                for (int j = 0; j < 4; ++j) {
                    float pv0 = __shfl_sync(0xffffffffu, tv0[j], (lane & ~3) + src);
                    int   pc0 = __shfl_sync(0xffffffffu, tc0[j], (lane & ~3) + src);
                    float pv1 = __shfl_sync(0xffffffffu, tv1[j], (lane & ~3) + src);
                    int   pc1 = __shfl_sync(0xffffffffu, tc1[j], (lane & ~3) + src);
                    if ((lane & 3) == 0) {
                        ins4(pv0, pc0, tv0, tc0);
                        ins4(pv1, pc1, tv1, tc1);
                    }
                }
            }
            if ((lane & 3) == 0) {
                int rA = (wid << 4) + (lane >> 2);
#pragma unroll
                for (int j = 0; j < 4; ++j) {
                    s_cand[rA * 4 + j]       = tc0[j];
                    s_cand[(rA + 8) * 4 + j] = tc1[j];
                }
            }
        }
        __syncthreads();

        // ---- exact top-4 rescore (reference-identical arithmetic) ---------
        if (tid < 128) {
            int row = tid;
            const float* rrow = g_resid + (size_t)(rowBase + row) * Dc;
            int c0 = s_cand[row * 4 + 0], c1 = s_cand[row * 4 + 1];
            int c2 = s_cand[row * 4 + 2], c3 = s_cand[row * 4 + 3];
            const float* w0 = cb + (size_t)(lRow + c0) * Dc;
            const float* w1 = cb + (size_t)(lRow + c1) * Dc;
            const float* w2 = cb + (size_t)(lRow + c2) * Dc;
            const float* w3 = cb + (size_t)(lRow + c3) * Dc;
            float d0 = 0.f, d1 = 0.f, d2 = 0.f, d3 = 0.f;
#pragma unroll 8
            for (int k = 0; k < Dc; ++k) {   // serial ascending FFMA == cuBLAS
                float r = rrow[k];
                d0 = fmaf(r, w0[k], d0);
                d1 = fmaf(r, w1[k], d1);
                d2 = fmaf(r, w2[k], d2);
                d3 = fmaf(r, w3[k], d3);
            }
            float rr = s_rr[row];
            float s0 = __fadd_rn(__fadd_rn(rr, __fmul_rn(-2.f, d0)), s_ww[c0]);
            float s1 = __fadd_rn(__fadd_rn(rr, __fmul_rn(-2.f, d1)), s_ww[c1]);
            float s2 = __fadd_rn(__fadd_rn(rr, __fmul_rn(-2.f, d2)), s_ww[c2]);
            float s3 = __fadd_rn(__fadd_rn(rr, __fmul_rn(-2.f, d3)), s_ww[c3]);
            float bs = s0; int bi = c0;
            if (s1 < bs || (s1 == bs && c1 < bi)) { bs = s1; bi = c1; }
            if (s2 < bs || (s2 == bs && c2 < bi)) { bs = s2; bi = c2; }
            if (s3 < bs || (s3 == bs && c3 < bi)) { bs = s3; bi = c3; }
            s_idx[row] = bi;
            int n = rowBase + row;
            int b = n >> 11;
            int t = n & 2047;
            dout[IDX_OFF + ((size_t)b * Lc + l) * Tc + t] = (float)bi;
        }
        __syncthreads();

        // ---- residual update: r -= W[sel] (exact fp32) --------------------
#pragma unroll
        for (int i = 0; i < 32; ++i) {
            int e = tid + i * 256;          // 8192 float4 units
            int row = e >> 6;
            int cc  = e & 63;
            float4* rp = (float4*)&g_resid[((size_t)(rowBase + row)) * Dc] + cc;
            const float4* wp = (const float4*)&cb[((size_t)(lRow + s_idx[row])) * Dc] + cc;
            float4 rv = *rp;
            float4 wv = *wp;
            rv.x -= wv.x; rv.y -= wv.y; rv.z -= wv.z; rv.w -= wv.w;
            *rp = rv;
        }
        __syncthreads();
    }
}

// ---------------------------------------------------------------------------
extern "C" void kernel_launch(void* const* d_in, const int* in_sizes, int n_in,
                              void* d_out, int out_size) {
    const float* x  = (const float*)d_in[0];
    const float* cb = (const float*)d_in[1];
    if (n_in >= 2 && in_sizes[0] == Lc * Kc * Dc && in_sizes[1] == Bc * Dc * Tc) {
        const float* tmp = x; x = cb; cb = tmp;
    }
    float* out = (float*)d_out;

    static int smem_set = 0;
    if (!smem_set) {
        cudaFuncSetAttribute(rvq_fused_kernel, cudaFuncAttributeMaxDynamicSharedMemorySize, SMEM_TOTAL);
        smem_set = 1;
    }

    // 1. codebook prep: fp16 copy + XLA-exact norms
    wprep_kernel<<<512, 256>>>(cb);
    wnorm_kernel<<<(Lc * Kc) / 2, 256>>>(cb);

    // 2. x -> residual (N, D)
    {
        dim3 grid(Tc / 32, Dc / 32, Bc);
        dim3 block(32, 8);
        transpose_in_kernel<<<grid, block>>>(x);
    }

    // 3. all 8 layers fused: HMMA prefilter + exact rescore + update
    rvq_fused_kernel<<<Nc / 128, 256, SMEM_TOTAL>>>(cb, out);

    // 4. out = x - final residual
    {
        dim3 grid(Tc / 32, Dc / 32, Bc);
        dim3 block(32, 8);
        finalize_kernel<<<grid, block>>>(x, out);
    }
}